// round 1
// baseline (speedup 1.0000x reference)
#include <cuda_runtime.h>
#include <cub/cub.cuh>
#include <math_constants.h>
#include <cstdint>

#define NA    36864      // 64*64*9 proposals
#define TOPK  6000
#define POST  2000
#define WORDS 94         // ceil(6000/64)
#define NMS_T 0.7f

// ---------------- static device scratch (no allocations allowed) ----------------
__device__ float4              g_props[NA];
__device__ unsigned long long  g_keys_in[NA];
__device__ unsigned long long  g_keys_out[NA];
__device__ unsigned char       g_temp[8u << 20];          // 8 MB CUB temp storage
__device__ float g_bx1[TOPK], g_by1[TOPK], g_bx2[TOPK], g_by2[TOPK];
__device__ float g_bsc[TOPK], g_bar[TOPK];
__device__ unsigned long long  g_mask[(size_t)TOPK * WORDS];

// anchor widths/heights: (ws,hs) per ratio {0.5:(23,12), 1:(16,16), 2:(11,22)} x scales {8,16,32}
__constant__ float c_aw[9] = {184.f,368.f,736.f,128.f,256.f,512.f, 88.f,176.f,352.f};
__constant__ float c_ah[9] = { 96.f,192.f,384.f,128.f,256.f,512.f,176.f,352.f,704.f};

// ---------------- 1) decode + filter + key pack ----------------
__global__ void decode_kernel(const float* __restrict__ dl, const float* __restrict__ sc)
{
    int i = blockIdx.x * blockDim.x + threadIdx.x;
    if (i >= NA) return;
    int pix = i / 9;              // h*64 + w
    int a   = i - pix * 9;
    int w   = pix & 63;
    int h   = pix >> 6;

    float s  = sc[(9 + a) * 4096 + pix];
    float d0 = dl[(a * 4 + 0) * 4096 + pix];
    float d1 = dl[(a * 4 + 1) * 4096 + pix];
    float d2 = dl[(a * 4 + 2) * 4096 + pix];
    float d3 = dl[(a * 4 + 3) * 4096 + pix];

    float aw = c_aw[a], ah = c_ah[a];
    float acx = (float)(16 * w + 8);
    float acy = (float)(16 * h + 8);

    // replicate reference fp32 op order exactly (no FMA contraction)
    float pcx = __fadd_rn(__fmul_rn(d0, aw), acx);
    float pcy = __fadd_rn(__fmul_rn(d1, ah), acy);
    float pw  = __fmul_rn(expf(d2), aw);
    float ph  = __fmul_rn(expf(d3), ah);
    float hw  = __fmul_rn(0.5f, pw);
    float hh  = __fmul_rn(0.5f, ph);

    float x1 = fminf(fmaxf(__fsub_rn(pcx, hw), 0.0f), 1023.0f);
    float y1 = fminf(fmaxf(__fsub_rn(pcy, hh), 0.0f), 1023.0f);
    float x2 = fminf(fmaxf(__fadd_rn(pcx, hw), 0.0f), 1023.0f);
    float y2 = fminf(fmaxf(__fadd_rn(pcy, hh), 0.0f), 1023.0f);

    g_props[i] = make_float4(x1, y1, x2, y2);

    bool keep = (__fadd_rn(__fsub_rn(x2, x1), 1.0f) >= 16.0f) &&
                (__fadd_rn(__fsub_rn(y2, y1), 1.0f) >= 16.0f);
    float sm = keep ? s : -CUDART_INF_F;

    unsigned int b   = __float_as_uint(sm);
    unsigned int ord = (b & 0x80000000u) ? ~b : (b | 0x80000000u);
    // descending sort on key -> score desc, then index asc (via ~i)
    g_keys_in[i] = ((unsigned long long)ord << 32) | (unsigned int)(~i);
}

// ---------------- 2) gather top-6000 into SoA ----------------
__global__ void gather_kernel()
{
    int t = blockIdx.x * blockDim.x + threadIdx.x;
    if (t >= TOPK) return;
    unsigned long long k = g_keys_out[t];
    unsigned int idx = ~(unsigned int)k;
    unsigned int ord = (unsigned int)(k >> 32);
    unsigned int b   = (ord & 0x80000000u) ? (ord & 0x7FFFFFFFu) : ~ord;
    float s = __uint_as_float(b);
    float4 p = g_props[idx];
    g_bx1[t] = p.x; g_by1[t] = p.y; g_bx2[t] = p.z; g_by2[t] = p.w;
    g_bsc[t] = s;
    g_bar[t] = __fmul_rn(__fadd_rn(__fsub_rn(p.z, p.x), 1.0f),
                         __fadd_rn(__fsub_rn(p.w, p.y), 1.0f));
}

// ---------------- 3) suppression bitmask matrix (upper triangle) ----------------
__global__ void nms_mask_kernel()
{
    int rb = blockIdx.y, cb = blockIdx.x;
    int tid = threadIdx.x;
    int i = rb * 64 + tid;
    if (cb < rb) {                       // below diagonal: zero-fill
        if (i < TOPK) g_mask[(size_t)i * WORDS + cb] = 0ULL;
        return;
    }
    __shared__ float sx1[64], sy1[64], sx2[64], sy2[64], sar[64];
    int j0 = cb * 64 + tid;
    if (j0 < TOPK) {
        sx1[tid] = g_bx1[j0]; sy1[tid] = g_by1[j0];
        sx2[tid] = g_bx2[j0]; sy2[tid] = g_by2[j0];
        sar[tid] = g_bar[j0];
    }
    __syncthreads();
    if (i >= TOPK) return;

    float ix1 = g_bx1[i], iy1 = g_by1[i], ix2 = g_bx2[i], iy2 = g_by2[i], ia = g_bar[i];
    int jmax = min(64, TOPK - cb * 64);
    unsigned long long m = 0ULL;
    #pragma unroll 4
    for (int kk = 0; kk < jmax; kk++) {
        int j = cb * 64 + kk;
        if (j <= i) continue;
        float iw = fmaxf(__fadd_rn(__fsub_rn(fminf(ix2, sx2[kk]), fmaxf(ix1, sx1[kk])), 1.0f), 0.0f);
        float ih = fmaxf(__fadd_rn(__fsub_rn(fminf(iy2, sy2[kk]), fmaxf(iy1, sy1[kk])), 1.0f), 0.0f);
        float inter = __fmul_rn(iw, ih);
        float iou = __fdiv_rn(inter, __fsub_rn(__fadd_rn(ia, sar[kk]), inter));
        if (iou > NMS_T) m |= (1ULL << kk);
    }
    g_mask[(size_t)i * WORDS + cb] = m;
}

// ---------------- 4) serial greedy scan + output write (one block) ----------------
__global__ void nms_scan_kernel(float* __restrict__ out)
{
    __shared__ unsigned long long removed[WORDS];
    int tid = threadIdx.x;
    if (tid < WORDS) removed[tid] = 0ULL;
    __syncthreads();

    float* blob = out;                 // (2000,5), col0 already zero
    float* outs = out + POST * 5;      // (2000,1)
    int count = 0;

    for (int i = 0; i < TOPK; i++) {
        unsigned long long wbits = removed[i >> 6];
        if ((wbits >> (i & 63)) & 1ULL) continue;      // suppressed
        float s = g_bsc[i];
        if (!isfinite(s)) continue;                    // -inf (filtered) -> never kept
        // kept: OR its suppression row
        if (tid < WORDS) removed[tid] |= g_mask[(size_t)i * WORDS + tid];
        if (tid == 0) {
            blob[count * 5 + 1] = g_bx1[i];
            blob[count * 5 + 2] = g_by1[i];
            blob[count * 5 + 3] = g_bx2[i];
            blob[count * 5 + 4] = g_by2[i];
            outs[count] = s;
        }
        count++;
        if (count == POST) break;                      // ranks >= 2000 never output
        __syncthreads();
    }
}

// ---------------- launch ----------------
extern "C" void kernel_launch(void* const* d_in, const int* in_sizes, int n_in,
                              void* d_out, int out_size)
{
    const float* deltas = (const float*)d_in[0];
    const float* scores = (const float*)d_in[1];
    float* out = (float*)d_out;

    cudaMemsetAsync(d_out, 0, (size_t)out_size * sizeof(float), 0);

    decode_kernel<<<(NA + 255) / 256, 256>>>(deltas, scores);

    void *d_temp = nullptr, *kin = nullptr, *kout = nullptr;
    cudaGetSymbolAddress(&d_temp, g_temp);
    cudaGetSymbolAddress(&kin,  g_keys_in);
    cudaGetSymbolAddress(&kout, g_keys_out);
    size_t tb = sizeof(g_temp);
    cub::DeviceRadixSort::SortKeysDescending(
        d_temp, tb,
        (const unsigned long long*)kin, (unsigned long long*)kout,
        NA, 0, 64, (cudaStream_t)0);

    gather_kernel<<<(TOPK + 255) / 256, 256>>>();

    dim3 grid(WORDS, WORDS);
    nms_mask_kernel<<<grid, 64>>>();

    nms_scan_kernel<<<1, 128>>>(out);
}

// round 2
// speedup vs baseline: 1.4903x; 1.4903x over previous
#include <cuda_runtime.h>
#include <cub/cub.cuh>
#include <math_constants.h>
#include <cstdint>

#define NA    36864      // 64*64*9 proposals
#define TOPK  6000
#define POST  2000
#define WORDS 94         // ceil(6000/64)
#define NMS_T 0.7f
#define SCAN_NTH 256

// ---------------- static device scratch (no allocations allowed) ----------------
__device__ float4              g_props[NA];
__device__ unsigned int        g_skey_in[NA],  g_skey_out[NA];
__device__ unsigned int        g_sidx_in[NA],  g_sidx_out[NA];
__device__ __align__(256) unsigned char g_temp[8u << 20];   // CUB temp storage
__device__ float g_bx1[TOPK], g_by1[TOPK], g_bx2[TOPK], g_by2[TOPK];
__device__ float g_bsc[TOPK], g_bar[TOPK];
__device__ unsigned long long  g_mask[(size_t)TOPK * WORDS];

// anchor widths/heights: ratio {0.5:(23,12), 1:(16,16), 2:(11,22)} x scales {8,16,32}
__constant__ float c_aw[9] = {184.f,368.f,736.f,128.f,256.f,512.f, 88.f,176.f,352.f};
__constant__ float c_ah[9] = { 96.f,192.f,384.f,128.f,256.f,512.f,176.f,352.f,704.f};

// ---------------- 1) decode + filter + key pack ----------------
__global__ void decode_kernel(const float* __restrict__ dl, const float* __restrict__ sc)
{
    int i = blockIdx.x * blockDim.x + threadIdx.x;
    if (i >= NA) return;
    int pix = i / 9;              // h*64 + w
    int a   = i - pix * 9;
    int w   = pix & 63;
    int h   = pix >> 6;

    float s  = sc[(9 + a) * 4096 + pix];
    float d0 = dl[(a * 4 + 0) * 4096 + pix];
    float d1 = dl[(a * 4 + 1) * 4096 + pix];
    float d2 = dl[(a * 4 + 2) * 4096 + pix];
    float d3 = dl[(a * 4 + 3) * 4096 + pix];

    float aw = c_aw[a], ah = c_ah[a];
    float acx = (float)(16 * w + 8);
    float acy = (float)(16 * h + 8);

    // replicate reference fp32 op order exactly (no FMA contraction)
    float pcx = __fadd_rn(__fmul_rn(d0, aw), acx);
    float pcy = __fadd_rn(__fmul_rn(d1, ah), acy);
    float pw  = __fmul_rn(expf(d2), aw);
    float ph  = __fmul_rn(expf(d3), ah);
    float hw  = __fmul_rn(0.5f, pw);
    float hh  = __fmul_rn(0.5f, ph);

    float x1 = fminf(fmaxf(__fsub_rn(pcx, hw), 0.0f), 1023.0f);
    float y1 = fminf(fmaxf(__fsub_rn(pcy, hh), 0.0f), 1023.0f);
    float x2 = fminf(fmaxf(__fadd_rn(pcx, hw), 0.0f), 1023.0f);
    float y2 = fminf(fmaxf(__fadd_rn(pcy, hh), 0.0f), 1023.0f);

    g_props[i] = make_float4(x1, y1, x2, y2);

    bool keep = (__fadd_rn(__fsub_rn(x2, x1), 1.0f) >= 16.0f) &&
                (__fadd_rn(__fsub_rn(y2, y1), 1.0f) >= 16.0f);
    float sm = keep ? s : -CUDART_INF_F;

    unsigned int b   = __float_as_uint(sm);
    unsigned int ord = (b & 0x80000000u) ? ~b : (b | 0x80000000u);
    g_skey_in[i] = ord;            // stable descending sort -> score desc, index asc on ties
    g_sidx_in[i] = (unsigned int)i;
}

// ---------------- 2) gather top-6000 into SoA ----------------
__global__ void gather_kernel()
{
    int t = blockIdx.x * blockDim.x + threadIdx.x;
    if (t >= TOPK) return;
    unsigned int idx = g_sidx_out[t];
    unsigned int ord = g_skey_out[t];
    unsigned int b   = (ord & 0x80000000u) ? (ord & 0x7FFFFFFFu) : ~ord;
    float s = __uint_as_float(b);
    float4 p = g_props[idx];
    g_bx1[t] = p.x; g_by1[t] = p.y; g_bx2[t] = p.z; g_by2[t] = p.w;
    g_bsc[t] = s;
    g_bar[t] = __fmul_rn(__fadd_rn(__fsub_rn(p.z, p.x), 1.0f),
                         __fadd_rn(__fsub_rn(p.w, p.y), 1.0f));
}

// ---------------- 3) suppression bitmask matrix (upper triangle only) ----------------
__global__ void nms_mask_kernel()
{
    int rb = blockIdx.y, cb = blockIdx.x;
    if (cb < rb) return;                 // lower triangle never read by scan
    int tid = threadIdx.x;
    int i = rb * 64 + tid;

    __shared__ float sx1[64], sy1[64], sx2[64], sy2[64], sar[64];
    int j0 = cb * 64 + tid;
    if (j0 < TOPK) {
        sx1[tid] = g_bx1[j0]; sy1[tid] = g_by1[j0];
        sx2[tid] = g_bx2[j0]; sy2[tid] = g_by2[j0];
        sar[tid] = g_bar[j0];
    }
    __syncthreads();
    if (i >= TOPK) return;

    float ix1 = g_bx1[i], iy1 = g_by1[i], ix2 = g_bx2[i], iy2 = g_by2[i], ia = g_bar[i];
    int jmax = min(64, TOPK - cb * 64);
    unsigned long long m = 0ULL;
    #pragma unroll 4
    for (int kk = 0; kk < jmax; kk++) {
        int j = cb * 64 + kk;
        if (j <= i) continue;
        float iw = fmaxf(__fadd_rn(__fsub_rn(fminf(ix2, sx2[kk]), fmaxf(ix1, sx1[kk])), 1.0f), 0.0f);
        float ih = fmaxf(__fadd_rn(__fsub_rn(fminf(iy2, sy2[kk]), fmaxf(iy1, sy1[kk])), 1.0f), 0.0f);
        float inter = __fmul_rn(iw, ih);
        float iou = __fdiv_rn(inter, __fsub_rn(__fadd_rn(ia, sar[kk]), inter));
        if (iou > NMS_T) m |= (1ULL << kk);
    }
    g_mask[(size_t)i * WORDS + cb] = m;
}

// ---------------- 4) blocked greedy scan (one block, latency-amortized) ----------------
__global__ void __launch_bounds__(SCAN_NTH) nms_scan_kernel(float* __restrict__ out)
{
    __shared__ unsigned long long removed[WORDS];
    __shared__ unsigned long long validm[WORDS + 2];   // padded to 6144 bits
    __shared__ unsigned long long sdiag[2][64];
    __shared__ int                slist[POST];
    __shared__ int                s_count;
    __shared__ unsigned long long s_keptbits;
    int tid = threadIdx.x;

    // build valid-bitmask (score finite) via warp ballot; 6144-bit padded loop
    for (int base = tid; base < (WORDS + 2) * 64; base += SCAN_NTH) {
        bool v = (base < TOPK) && isfinite(g_bsc[base]);
        unsigned int bal = __ballot_sync(0xFFFFFFFFu, v);
        if ((tid & 31) == 0) ((unsigned int*)validm)[base >> 5] = bal;
    }
    if (tid < WORDS) removed[tid] = 0ULL;
    if (tid == 0) s_count = 0;
    if (tid < 64) sdiag[0][tid] = g_mask[(size_t)tid * WORDS + 0];   // diag block 0
    __syncthreads();

    int count = 0;
    for (int w = 0; w < WORDS; w++) {
        // Phase B: resolve within-word greedy chain from shared only (1 thread)
        if (tid == 0) {
            unsigned long long alive = validm[w] & ~removed[w];
            unsigned long long kept  = 0ULL;
            int c = s_count;
            const unsigned long long* diag = sdiag[w & 1];
            while (alive && c < POST) {
                int b = __ffsll(alive) - 1;
                kept |= 1ULL << b;
                slist[c++] = w * 64 + b;
                alive &= ~diag[b];
                alive &= ~(1ULL << b);
            }
            s_keptbits = kept;
            s_count = c;
        }
        __syncthreads();
        unsigned long long kept = s_keptbits;
        count = s_count;

        // Phase C: threads 0..127 OR kept rows into removed[w+1..]; 128..191 prefetch next diag
        if (tid >= 128 && tid < 192 && w + 1 < WORDS)
            sdiag[(w + 1) & 1][tid - 128] =
                g_mask[(size_t)((w + 1) * 64 + (tid - 128)) * WORDS + (w + 1)];
        if (tid < 128 && kept) {
            int wp = w + 1 + tid;
            if (wp < WORDS) {
                unsigned long long acc = 0ULL, kk = kept;
                while (kk) {
                    int b = __ffsll(kk) - 1; kk &= kk - 1;
                    acc |= g_mask[(size_t)(w * 64 + b) * WORDS + wp];
                }
                removed[wp] |= acc;
            }
        }
        __syncthreads();
        if (count >= POST) break;
    }

    // Phase D: parallel output write
    int total = min(count, POST);
    float* blob = out;                 // (2000,5), col0 + tail rows already zeroed
    float* outs = out + POST * 5;      // (2000,1)
    for (int t = tid; t < total; t += SCAN_NTH) {
        int i = slist[t];
        blob[t * 5 + 1] = g_bx1[i];
        blob[t * 5 + 2] = g_by1[i];
        blob[t * 5 + 3] = g_bx2[i];
        blob[t * 5 + 4] = g_by2[i];
        outs[t] = g_bsc[i];
    }
}

// ---------------- launch ----------------
extern "C" void kernel_launch(void* const* d_in, const int* in_sizes, int n_in,
                              void* d_out, int out_size)
{
    const float* deltas = (const float*)d_in[0];
    const float* scores = (const float*)d_in[1];
    float* out = (float*)d_out;

    cudaMemsetAsync(d_out, 0, (size_t)out_size * sizeof(float), 0);

    decode_kernel<<<(NA + 255) / 256, 256>>>(deltas, scores);

    void *d_temp = nullptr, *kin = nullptr, *kout = nullptr, *vin = nullptr, *vout = nullptr;
    cudaGetSymbolAddress(&d_temp, g_temp);
    cudaGetSymbolAddress(&kin,  g_skey_in);
    cudaGetSymbolAddress(&kout, g_skey_out);
    cudaGetSymbolAddress(&vin,  g_sidx_in);
    cudaGetSymbolAddress(&vout, g_sidx_out);
    size_t tb = sizeof(g_temp);
    cub::DeviceRadixSort::SortPairsDescending(
        d_temp, tb,
        (const unsigned int*)kin, (unsigned int*)kout,
        (const unsigned int*)vin, (unsigned int*)vout,
        NA, 0, 32, (cudaStream_t)0);

    gather_kernel<<<(TOPK + 255) / 256, 256>>>();

    dim3 grid(WORDS, WORDS);
    nms_mask_kernel<<<grid, 64>>>();

    nms_scan_kernel<<<1, SCAN_NTH>>>(out);
}

// round 3
// speedup vs baseline: 3.2040x; 2.1499x over previous
#include <cuda_runtime.h>
#include <cub/cub.cuh>
#include <math_constants.h>
#include <cstdint>

#define NA    36864      // 64*64*9 proposals
#define TOPK  6000
#define POST  2000
#define WORDS 94         // ceil(6000/64)
#define NMS_T 0.7f
#define SCAN_NTH 256

// ---------------- static device scratch (no allocations allowed) ----------------
__device__ float4              g_props[NA];
__device__ unsigned int        g_skey_in[NA],  g_skey_out[NA];
__device__ unsigned int        g_sidx_in[NA],  g_sidx_out[NA];
__device__ __align__(256) unsigned char g_temp[8u << 20];   // CUB temp storage
__device__ float g_bx1[TOPK], g_by1[TOPK], g_bx2[TOPK], g_by2[TOPK];
__device__ float g_bsc[TOPK], g_bar[TOPK];
__device__ unsigned long long  g_mask[(size_t)TOPK * WORDS];
__device__ ulonglong2          g_re[TOPK][WORDS];   // sparse row entries {bits, word}
__device__ int                 g_rcnt[TOPK];        // entries per row

// anchor widths/heights: ratio {0.5:(23,12), 1:(16,16), 2:(11,22)} x scales {8,16,32}
__constant__ float c_aw[9] = {184.f,368.f,736.f,128.f,256.f,512.f, 88.f,176.f,352.f};
__constant__ float c_ah[9] = { 96.f,192.f,384.f,128.f,256.f,512.f,176.f,352.f,704.f};

// ---------------- 1) decode + filter + key pack ----------------
__global__ void decode_kernel(const float* __restrict__ dl, const float* __restrict__ sc)
{
    int i = blockIdx.x * blockDim.x + threadIdx.x;
    if (i >= NA) return;
    int pix = i / 9;              // h*64 + w
    int a   = i - pix * 9;
    int w   = pix & 63;
    int h   = pix >> 6;

    float s  = sc[(9 + a) * 4096 + pix];
    float d0 = dl[(a * 4 + 0) * 4096 + pix];
    float d1 = dl[(a * 4 + 1) * 4096 + pix];
    float d2 = dl[(a * 4 + 2) * 4096 + pix];
    float d3 = dl[(a * 4 + 3) * 4096 + pix];

    float aw = c_aw[a], ah = c_ah[a];
    float acx = (float)(16 * w + 8);
    float acy = (float)(16 * h + 8);

    // replicate reference fp32 op order exactly (no FMA contraction)
    float pcx = __fadd_rn(__fmul_rn(d0, aw), acx);
    float pcy = __fadd_rn(__fmul_rn(d1, ah), acy);
    float pw  = __fmul_rn(expf(d2), aw);
    float ph  = __fmul_rn(expf(d3), ah);
    float hw  = __fmul_rn(0.5f, pw);
    float hh  = __fmul_rn(0.5f, ph);

    float x1 = fminf(fmaxf(__fsub_rn(pcx, hw), 0.0f), 1023.0f);
    float y1 = fminf(fmaxf(__fsub_rn(pcy, hh), 0.0f), 1023.0f);
    float x2 = fminf(fmaxf(__fadd_rn(pcx, hw), 0.0f), 1023.0f);
    float y2 = fminf(fmaxf(__fadd_rn(pcy, hh), 0.0f), 1023.0f);

    g_props[i] = make_float4(x1, y1, x2, y2);

    bool keep = (__fadd_rn(__fsub_rn(x2, x1), 1.0f) >= 16.0f) &&
                (__fadd_rn(__fsub_rn(y2, y1), 1.0f) >= 16.0f);
    float sm = keep ? s : -CUDART_INF_F;

    unsigned int b   = __float_as_uint(sm);
    unsigned int ord = (b & 0x80000000u) ? ~b : (b | 0x80000000u);
    g_skey_in[i] = ord;            // stable descending sort -> score desc, index asc on ties
    g_sidx_in[i] = (unsigned int)i;
}

// ---------------- 2) gather top-6000 into SoA ----------------
__global__ void gather_kernel()
{
    int t = blockIdx.x * blockDim.x + threadIdx.x;
    if (t >= TOPK) return;
    unsigned int idx = g_sidx_out[t];
    unsigned int ord = g_skey_out[t];
    unsigned int b   = (ord & 0x80000000u) ? (ord & 0x7FFFFFFFu) : ~ord;
    float s = __uint_as_float(b);
    float4 p = g_props[idx];
    g_bx1[t] = p.x; g_by1[t] = p.y; g_bx2[t] = p.z; g_by2[t] = p.w;
    g_bsc[t] = s;
    g_bar[t] = __fmul_rn(__fadd_rn(__fsub_rn(p.z, p.x), 1.0f),
                         __fadd_rn(__fsub_rn(p.w, p.y), 1.0f));
}

// ---------------- 3) suppression bitmask matrix (upper triangle only) ----------------
__global__ void nms_mask_kernel()
{
    int rb = blockIdx.y, cb = blockIdx.x;
    if (cb < rb) return;                 // lower triangle never read
    int tid = threadIdx.x;
    int i = rb * 64 + tid;

    __shared__ float sx1[64], sy1[64], sx2[64], sy2[64], sar[64];
    int j0 = cb * 64 + tid;
    if (j0 < TOPK) {
        sx1[tid] = g_bx1[j0]; sy1[tid] = g_by1[j0];
        sx2[tid] = g_bx2[j0]; sy2[tid] = g_by2[j0];
        sar[tid] = g_bar[j0];
    }
    __syncthreads();
    if (i >= TOPK) return;

    float ix1 = g_bx1[i], iy1 = g_by1[i], ix2 = g_bx2[i], iy2 = g_by2[i], ia = g_bar[i];
    int jmax = min(64, TOPK - cb * 64);
    unsigned long long m = 0ULL;
    #pragma unroll 4
    for (int kk = 0; kk < jmax; kk++) {
        int j = cb * 64 + kk;
        if (j <= i) continue;
        float iw = fmaxf(__fadd_rn(__fsub_rn(fminf(ix2, sx2[kk]), fmaxf(ix1, sx1[kk])), 1.0f), 0.0f);
        float ih = fmaxf(__fadd_rn(__fsub_rn(fminf(iy2, sy2[kk]), fmaxf(iy1, sy1[kk])), 1.0f), 0.0f);
        float inter = __fmul_rn(iw, ih);
        float iou = __fdiv_rn(inter, __fsub_rn(__fadd_rn(ia, sar[kk]), inter));
        if (iou > NMS_T) m |= (1ULL << kk);
    }
    g_mask[(size_t)i * WORDS + cb] = m;
}

// ---------------- 3b) compress rows to sparse (word,bits) entry lists ----------------
__global__ void compress_kernel()
{
    int i    = (blockIdx.x * blockDim.x + threadIdx.x) >> 5;   // one warp per row
    int lane = threadIdx.x & 31;
    if (i >= TOPK) return;
    int wown = i >> 6;
    int cnt = 0;
    #pragma unroll
    for (int base = 0; base < WORDS + 31; base += 32) {
        int wd = base + lane;
        unsigned long long m = 0ULL;
        if (wd < WORDS && wd > wown) m = g_mask[(size_t)i * WORDS + wd];
        unsigned int bal = __ballot_sync(0xFFFFFFFFu, m != 0ULL);
        if (m != 0ULL) {
            int pos = cnt + __popc(bal & ((1u << lane) - 1u));
            g_re[i][pos] = make_ulonglong2(m, (unsigned long long)wd);
        }
        cnt += __popc(bal);
        if (base + 32 >= WORDS) break;
    }
    if (lane == 0) g_rcnt[i] = cnt;
}

// ---------------- 4) blocked greedy scan (one block, sparse application) ----------------
__global__ void __launch_bounds__(SCAN_NTH) nms_scan_kernel(float* __restrict__ out)
{
    __shared__ unsigned long long removed[WORDS];
    __shared__ unsigned long long validm[WORDS + 2];   // padded to 6144 bits
    __shared__ unsigned long long sdiag[2][64];
    __shared__ unsigned int       s_rownz[2][2];       // which diag rows are nonzero
    __shared__ int                slist[POST];
    __shared__ int                s_count, s_c0;
    int tid  = threadIdx.x;
    int wid  = tid >> 5;
    int lane = tid & 31;

    // valid-bitmask (score finite) via warp ballot over padded 6144 bits
    for (int base = tid; base < (WORDS + 2) * 64; base += SCAN_NTH) {
        bool v = (base < TOPK) && isfinite(g_bsc[base]);
        unsigned int bal = __ballot_sync(0xFFFFFFFFu, v);
        if ((tid & 31) == 0) ((unsigned int*)validm)[base >> 5] = bal;
    }
    if (tid < WORDS) removed[tid] = 0ULL;
    if (tid == 0) { s_count = 0; s_c0 = 0; }
    if (tid >= 192) {                                   // prefetch diag block 0 + nz flags
        int t = tid - 192;
        unsigned long long dm = g_mask[(size_t)t * WORDS + 0];
        sdiag[0][t] = dm;
        unsigned int bal = __ballot_sync(0xFFFFFFFFu, dm != 0ULL);
        if (lane == 0) s_rownz[0][wid - 6] = bal;
    }
    __syncthreads();

    int count = 0;
    for (int w = 0; w < WORDS; w++) {
        // Phase B: thread 0 resolves within-word greedy chain (mostly ALU, rare shared load)
        if (tid == 0) {
            unsigned long long alive = validm[w] & ~removed[w];
            unsigned long long rn = ((unsigned long long)s_rownz[w & 1][1] << 32) |
                                     s_rownz[w & 1][0];
            const unsigned long long* diag = sdiag[w & 1];
            int c = s_count;
            s_c0 = c;
            while (alive && c < POST) {
                int b = __ffsll(alive) - 1;
                unsigned long long bit = 1ULL << b;
                slist[c++] = w * 64 + b;
                alive &= ~bit;
                if (rn & bit) alive &= ~diag[b];
            }
            s_count = c;
        }
        __syncthreads();
        count = s_count;
        int c0 = s_c0;
        if (count >= POST) break;                       // no further output possible

        // Phase C: warps 0..5 apply sparse rows of kept boxes; warps 6..7 prefetch next diag
        if (tid >= 192) {
            if (w + 1 < WORDS) {
                int t = tid - 192;
                int row = (w + 1) * 64 + t;
                unsigned long long dm = (row < TOPK)
                    ? g_mask[(size_t)row * WORDS + (w + 1)] : 0ULL;
                sdiag[(w + 1) & 1][t] = dm;
                unsigned int bal = __ballot_sync(0xFFFFFFFFu, dm != 0ULL);
                if (lane == 0) s_rownz[(w + 1) & 1][wid - 6] = bal;
            }
        } else {
            for (int k = c0 + wid; k < count; k += 6) {
                int idx = slist[k];
                int cnt = g_rcnt[idx];
                for (int e = lane; e < cnt; e += 32) {
                    ulonglong2 ent = g_re[idx][e];
                    atomicOr(&removed[(int)ent.y], ent.x);
                }
            }
        }
        __syncthreads();
    }

    // Phase D: parallel output write
    int total = min(count, POST);
    float* blob = out;                 // (2000,5), col0 + tail rows already zeroed
    float* outs = out + POST * 5;      // (2000,1)
    for (int t = tid; t < total; t += SCAN_NTH) {
        int i = slist[t];
        blob[t * 5 + 1] = g_bx1[i];
        blob[t * 5 + 2] = g_by1[i];
        blob[t * 5 + 3] = g_bx2[i];
        blob[t * 5 + 4] = g_by2[i];
        outs[t] = g_bsc[i];
    }
}

// ---------------- launch ----------------
extern "C" void kernel_launch(void* const* d_in, const int* in_sizes, int n_in,
                              void* d_out, int out_size)
{
    const float* deltas = (const float*)d_in[0];
    const float* scores = (const float*)d_in[1];
    float* out = (float*)d_out;

    cudaMemsetAsync(d_out, 0, (size_t)out_size * sizeof(float), 0);

    decode_kernel<<<(NA + 255) / 256, 256>>>(deltas, scores);

    void *d_temp = nullptr, *kin = nullptr, *kout = nullptr, *vin = nullptr, *vout = nullptr;
    cudaGetSymbolAddress(&d_temp, g_temp);
    cudaGetSymbolAddress(&kin,  g_skey_in);
    cudaGetSymbolAddress(&kout, g_skey_out);
    cudaGetSymbolAddress(&vin,  g_sidx_in);
    cudaGetSymbolAddress(&vout, g_sidx_out);
    size_t tb = sizeof(g_temp);
    cub::DeviceRadixSort::SortPairsDescending(
        d_temp, tb,
        (const unsigned int*)kin, (unsigned int*)kout,
        (const unsigned int*)vin, (unsigned int*)vout,
        NA, 0, 32, (cudaStream_t)0);

    gather_kernel<<<(TOPK + 255) / 256, 256>>>();

    dim3 grid(WORDS, WORDS);
    nms_mask_kernel<<<grid, 64>>>();

    compress_kernel<<<(TOPK * 32 + 255) / 256, 256>>>();

    nms_scan_kernel<<<1, SCAN_NTH>>>(out);
}

// round 4
// speedup vs baseline: 3.4978x; 1.0917x over previous
#include <cuda_runtime.h>
#include <cub/cub.cuh>
#include <math_constants.h>
#include <cstdint>

#define NA    36864      // 64*64*9 proposals
#define TOPK  6000
#define POST  2000
#define WORDS 94         // ceil(6000/64)
#define W1    47         // stage-1 word count
#define R1    (W1*64)    // 3008 stage-1 candidates
#define NCAP  8192       // compacted sort capacity
#define NBINS 1024

typedef unsigned long long ull;

// ---------------- static device scratch (no allocations allowed) ----------------
__device__ float4   g_props[NA];
__device__ unsigned g_skey[NA];
__device__ unsigned g_hist[NBINS + 1];      // [NBINS] = compact counter
__device__ int      g_B;
__device__ ull      g_k64in[NCAP], g_k64out[NCAP];
__device__ __align__(256) unsigned char g_temp[4u << 20];
__device__ float4   g_box[TOPK];
__device__ float    g_bar[TOPK], g_bsc[TOPK];
__device__ ull      g_validm[96];
__device__ ull      g_mask[(size_t)TOPK * WORDS];
__device__ ulonglong2 g_re1[(size_t)R1 * W1];
__device__ int      g_rcnt1[R1];
__device__ ulonglong2 g_re2[(size_t)TOPK * W1];
__device__ int      g_rcnt2[TOPK];
__device__ int      g_slist[POST];
__device__ int      g_count;
__device__ int      g_need2;

// anchor widths/heights: ratio {0.5:(23,12), 1:(16,16), 2:(11,22)} x scales {8,16,32}
__constant__ float c_aw[9] = {184.f,368.f,736.f,128.f,256.f,512.f, 88.f,176.f,352.f};
__constant__ float c_ah[9] = { 96.f,192.f,384.f,128.f,256.f,512.f,176.f,352.f,704.f};

// ---------------- 1) decode + filter + key pack + score histogram ----------------
__global__ void decode_kernel(const float* __restrict__ dl, const float* __restrict__ sc)
{
    int i = blockIdx.x * blockDim.x + threadIdx.x;
    if (i >= NA) return;
    int pix = i / 9;              // h*64 + w
    int a   = i - pix * 9;
    int w   = pix & 63;
    int h   = pix >> 6;

    float s  = sc[(9 + a) * 4096 + pix];
    float d0 = dl[(a * 4 + 0) * 4096 + pix];
    float d1 = dl[(a * 4 + 1) * 4096 + pix];
    float d2 = dl[(a * 4 + 2) * 4096 + pix];
    float d3 = dl[(a * 4 + 3) * 4096 + pix];

    float aw = c_aw[a], ah = c_ah[a];
    float acx = (float)(16 * w + 8);
    float acy = (float)(16 * h + 8);

    // replicate reference fp32 op order exactly (no FMA contraction)
    float pcx = __fadd_rn(__fmul_rn(d0, aw), acx);
    float pcy = __fadd_rn(__fmul_rn(d1, ah), acy);
    float pw  = __fmul_rn(expf(d2), aw);
    float ph  = __fmul_rn(expf(d3), ah);
    float hw  = __fmul_rn(0.5f, pw);
    float hh  = __fmul_rn(0.5f, ph);

    float x1 = fminf(fmaxf(__fsub_rn(pcx, hw), 0.0f), 1023.0f);
    float y1 = fminf(fmaxf(__fsub_rn(pcy, hh), 0.0f), 1023.0f);
    float x2 = fminf(fmaxf(__fadd_rn(pcx, hw), 0.0f), 1023.0f);
    float y2 = fminf(fmaxf(__fadd_rn(pcy, hh), 0.0f), 1023.0f);

    g_props[i] = make_float4(x1, y1, x2, y2);

    bool keep = (__fadd_rn(__fsub_rn(x2, x1), 1.0f) >= 16.0f) &&
                (__fadd_rn(__fsub_rn(y2, y1), 1.0f) >= 16.0f);
    float sm = keep ? s : -CUDART_INF_F;

    unsigned b   = __float_as_uint(sm);
    unsigned ord = (b & 0x80000000u) ? ~b : (b | 0x80000000u);
    g_skey[i] = ord;
    if (keep) {
        int bin = min(NBINS - 1, (int)(s * (float)NBINS));   // s in [0,1)
        atomicAdd(&g_hist[bin], 1u);
    }
}

// ---------------- 1b) threshold bin: largest B with suffix-count >= TOPK ----------------
__global__ void thresh_kernel()
{
    __shared__ unsigned sh[NBINS];
    __shared__ int sB;
    int t = threadIdx.x;
    sh[t] = g_hist[t];
    if (t == 0) sB = 0;
    __syncthreads();
    for (int off = 1; off < NBINS; off <<= 1) {
        unsigned v = sh[t] + ((t + off < NBINS) ? sh[t + off] : 0u);
        __syncthreads();
        sh[t] = v;
        __syncthreads();
    }
    if (sh[t] >= TOPK) atomicMax(&sB, t);
    __syncthreads();
    if (t == 0) g_B = sB;
}

// ---------------- 1c) compact candidates above threshold bin ----------------
__global__ void compact_kernel()
{
    int i = blockIdx.x * blockDim.x + threadIdx.x;
    if (i >= NA) return;
    unsigned ord = g_skey[i];
    if (!(ord & 0x80000000u)) return;             // filtered (-inf)
    float s = __uint_as_float(ord & 0x7FFFFFFFu);
    int bin = min(NBINS - 1, (int)(s * (float)NBINS));
    if (bin < g_B) return;
    unsigned pos = atomicAdd(&g_hist[NBINS], 1u);
    if (pos < NCAP)
        g_k64in[pos] = ((ull)ord << 16) | (unsigned)((~i) & 0xFFFF);  // NA < 65536
}

// ---------------- 2) gather top-6000 into SoA + valid bitmask ----------------
__global__ void gather_kernel()
{
    int t = blockIdx.x * blockDim.x + threadIdx.x;   // 6144 threads
    float s; float4 p = make_float4(0.f, 0.f, 0.f, 0.f);
    if (t < TOPK) {
        ull k = g_k64out[t];
        unsigned idx = (~(unsigned)k) & 0xFFFFu;
        unsigned ord = (unsigned)(k >> 16);
        unsigned b   = (ord & 0x80000000u) ? (ord & 0x7FFFFFFFu) : ~ord;
        s = __uint_as_float(b);
        if (idx < NA) p = g_props[idx];
        else s = CUDART_NAN_F;                       // padding slot (shouldn't reach top-6000)
    } else s = CUDART_NAN_F;
    bool v = isfinite(s);
    unsigned bal = __ballot_sync(0xFFFFFFFFu, v);
    if ((t & 31) == 0) ((unsigned*)g_validm)[t >> 5] = bal;
    if (t < TOPK) {
        g_box[t] = p; g_bsc[t] = s;
        g_bar[t] = __fmul_rn(__fadd_rn(__fsub_rn(p.z, p.x), 1.0f),
                             __fadd_rn(__fsub_rn(p.w, p.y), 1.0f));
    }
}

// ---------------- 3) suppression bitmask tiles (4 rows/thread, guarded fast-div) ----------------
__global__ void mask_kernel(int wdStart, int rowLimit, int checkFlag)
{
    if (checkFlag && !g_need2) return;
    int wd = wdStart + blockIdx.x;
    int rowBase = blockIdx.y * 256;
    if (rowBase >= (wd + 1) * 64) return;           // tile fully below diagonal
    int tid = threadIdx.x;

    __shared__ float4 sc4[64];
    __shared__ float  scar[64];
    int j = wd * 64 + tid;
    if (j < TOPK) { sc4[tid] = g_box[j]; scar[tid] = g_bar[j]; }
    else { sc4[tid] = make_float4(3e9f, 3e9f, -3e9f, -3e9f); scar[tid] = 1.0f; }
    __syncthreads();

    float4 rb[4]; float rar[4]; ull acc[4], allowed[4]; int irow[4]; bool valid[4];
    #pragma unroll
    for (int r = 0; r < 4; r++) {
        int i = rowBase + r * 64 + tid;
        irow[r] = i;
        bool v = (i < rowLimit);
        valid[r] = v;
        rb[r]  = v ? g_box[i] : make_float4(3e9f, 3e9f, -3e9f, -3e9f);
        rar[r] = v ? g_bar[i] : 1.0f;
        int sh = i - wd * 64 + 1;                   // keep bits kk >= sh (j > i)
        allowed[r] = (sh <= 0) ? ~0ULL : (sh >= 64 ? 0ULL : (~0ULL << sh));
        acc[r] = 0ULL;
    }

    #pragma unroll 4
    for (int kk = 0; kk < 64; kk++) {
        float4 c = sc4[kk]; float car = scar[kk];
        #pragma unroll
        for (int r = 0; r < 4; r++) {
            float iw = fmaxf(__fadd_rn(__fsub_rn(fminf(rb[r].z, c.z), fmaxf(rb[r].x, c.x)), 1.0f), 0.0f);
            float ih = fmaxf(__fadd_rn(__fsub_rn(fminf(rb[r].w, c.w), fmaxf(rb[r].y, c.y)), 1.0f), 0.0f);
            float inter = __fmul_rn(iw, ih);
            float un = __fsub_rn(__fadd_rn(rar[r], car), inter);
            float t = 0.7f * un;
            bool sup;
            if (inter > t * 1.0001f)       sup = true;    // surely > 0.7
            else if (inter <= t * 0.9999f) sup = false;   // surely <= 0.7
            else sup = (__fdiv_rn(inter, un) > 0.7f);     // rare exact path
            if (sup) acc[r] |= (1ULL << kk);
        }
    }
    #pragma unroll
    for (int r = 0; r < 4; r++)
        if (valid[r]) g_mask[(size_t)irow[r] * WORDS + wd] = acc[r] & allowed[r];
}

// ---------------- 3b) compress rows to sparse (word,bits) entry lists ----------------
__global__ void compress_kernel(int mode)     // 0: rows<R1, wd<W1   1: all rows, wd>=W1
{
    if (mode && !g_need2) return;
    int gi = blockIdx.x * blockDim.x + threadIdx.x;
    int i = gi >> 5, lane = gi & 31;
    int rowLimit = mode ? TOPK : R1;
    if (i >= rowLimit) return;
    int wdStart = mode ? W1 : 0;
    int wdEnd   = mode ? WORDS : W1;
    ulonglong2* re = mode ? g_re2 : g_re1;
    int* rcnt      = mode ? g_rcnt2 : g_rcnt1;
    int wlo = max((i >> 6) + 1, wdStart);
    int cnt = 0;
    for (int base = wlo; base < wdEnd; base += 32) {
        int wd = base + lane;
        ull m = (wd < wdEnd) ? g_mask[(size_t)i * WORDS + wd] : 0ULL;
        unsigned bal = __ballot_sync(0xFFFFFFFFu, m != 0ULL);
        if (m) re[(size_t)i * W1 + cnt + __popc(bal & ((1u << lane) - 1u))] =
                   make_ulonglong2(m, (ull)wd);
        cnt += __popc(bal);
    }
    if (!lane) rcnt[i] = cnt;
}

// ---------------- 4a) stage-1 scan: words 0..46 ----------------
__global__ void __launch_bounds__(256) scan1_kernel()
{
    __shared__ ull removed[W1];
    __shared__ ull sval[W1];
    __shared__ ull sdiag[2][64];
    __shared__ unsigned s_rownz[2][2];
    __shared__ int s_count, s_c0;
    int tid = threadIdx.x, wid = tid >> 5, lane = tid & 31;

    if (tid < W1) { removed[tid] = 0ULL; sval[tid] = g_validm[tid]; }
    if (!tid) { s_count = 0; s_c0 = 0; }
    if (tid >= 192) {
        int t = tid - 192;
        ull dm = g_mask[(size_t)t * WORDS + 0];
        sdiag[0][t] = dm;
        unsigned bal = __ballot_sync(0xFFFFFFFFu, dm != 0ULL);
        if (!lane) s_rownz[0][wid - 6] = bal;
    }
    __syncthreads();

    int count = 0;
    for (int w = 0; w < W1; w++) {
        if (!tid) {
            ull alive = sval[w] & ~removed[w];
            ull rn = ((ull)s_rownz[w & 1][1] << 32) | s_rownz[w & 1][0];
            const ull* diag = sdiag[w & 1];
            int c = s_count; s_c0 = c;
            while (alive && c < POST) {
                int b = __ffsll(alive) - 1;
                ull bit = 1ULL << b;
                g_slist[c++] = w * 64 + b;
                alive &= ~bit;
                if (rn & bit) alive &= ~diag[b];
            }
            s_count = c;
        }
        __syncthreads();
        count = s_count;
        int c0 = s_c0;
        if (count >= POST) break;

        if (tid >= 192) {
            if (w + 1 < W1) {
                int t = tid - 192;
                ull dm = g_mask[(size_t)((w + 1) * 64 + t) * WORDS + (w + 1)];
                sdiag[(w + 1) & 1][t] = dm;
                unsigned bal = __ballot_sync(0xFFFFFFFFu, dm != 0ULL);
                if (!lane) s_rownz[(w + 1) & 1][wid - 6] = bal;
            }
        } else {
            for (int k = c0 + wid; k < count; k += 6) {
                int idx = g_slist[k];
                int cnt = g_rcnt1[idx];
                for (int e = lane; e < cnt; e += 32) {
                    ulonglong2 ent = g_re1[(size_t)idx * W1 + e];
                    atomicOr(&removed[(int)ent.y], ent.x);
                }
            }
        }
        __syncthreads();
    }
    if (!tid) { g_count = count; g_need2 = (count < POST) ? 1 : 0; }
}

// ---------------- 4b) stage-2 scan (resume if needed) + output ----------------
__global__ void __launch_bounds__(256) scan2_kernel(float* __restrict__ out)
{
    __shared__ ull removed[WORDS];
    __shared__ ull sval[WORDS - W1];
    __shared__ ull sdiag[2][64];
    __shared__ unsigned s_rownz[2][2];
    __shared__ int s_count, s_c0;
    int tid = threadIdx.x, wid = tid >> 5, lane = tid & 31;
    int count = g_count;

    if (g_need2) {
        if (tid < WORDS) removed[tid] = 0ULL;
        if (tid < WORDS - W1) sval[tid] = g_validm[W1 + tid];
        if (!tid) { s_count = count; s_c0 = count; }
        __syncthreads();
        // re-apply stage-1 kept boxes' suppression of words >= W1
        for (int k = wid; k < count; k += 8) {
            int idx = g_slist[k];
            int cnt = g_rcnt2[idx];
            for (int e = lane; e < cnt; e += 32) {
                ulonglong2 ent = g_re2[(size_t)idx * W1 + e];
                atomicOr(&removed[(int)ent.y], ent.x);
            }
        }
        __syncthreads();
        if (tid >= 192) {
            int t = tid - 192;
            int row = W1 * 64 + t;
            ull dm = (row < TOPK) ? g_mask[(size_t)row * WORDS + W1] : 0ULL;
            sdiag[W1 & 1][t] = dm;
            unsigned bal = __ballot_sync(0xFFFFFFFFu, dm != 0ULL);
            if (!lane) s_rownz[W1 & 1][wid - 6] = bal;
        }
        __syncthreads();

        for (int w = W1; w < WORDS; w++) {
            if (!tid) {
                ull alive = sval[w - W1] & ~removed[w];
                ull rn = ((ull)s_rownz[w & 1][1] << 32) | s_rownz[w & 1][0];
                const ull* diag = sdiag[w & 1];
                int c = s_count; s_c0 = c;
                while (alive && c < POST) {
                    int b = __ffsll(alive) - 1;
                    ull bit = 1ULL << b;
                    g_slist[c++] = w * 64 + b;
                    alive &= ~bit;
                    if (rn & bit) alive &= ~diag[b];
                }
                s_count = c;
            }
            __syncthreads();
            count = s_count;
            int c0 = s_c0;
            if (count >= POST) break;

            if (tid >= 192) {
                if (w + 1 < WORDS) {
                    int t = tid - 192;
                    int row = (w + 1) * 64 + t;
                    ull dm = (row < TOPK) ? g_mask[(size_t)row * WORDS + (w + 1)] : 0ULL;
                    sdiag[(w + 1) & 1][t] = dm;
                    unsigned bal = __ballot_sync(0xFFFFFFFFu, dm != 0ULL);
                    if (!lane) s_rownz[(w + 1) & 1][wid - 6] = bal;
                }
            } else {
                for (int k = c0 + wid; k < count; k += 6) {
                    int idx = g_slist[k];
                    int cnt = g_rcnt2[idx];
                    for (int e = lane; e < cnt; e += 32) {
                        ulonglong2 ent = g_re2[(size_t)idx * W1 + e];
                        atomicOr(&removed[(int)ent.y], ent.x);
                    }
                }
            }
            __syncthreads();
        }
        __syncthreads();
    }

    // output (always here)
    int total = min(count, POST);
    float* outs = out + POST * 5;
    for (int t = tid; t < total; t += 256) {
        int i = g_slist[t];
        float4 p = g_box[i];
        out[t * 5 + 1] = p.x; out[t * 5 + 2] = p.y;
        out[t * 5 + 3] = p.z; out[t * 5 + 4] = p.w;
        outs[t] = g_bsc[i];
    }
}

// ---------------- launch ----------------
extern "C" void kernel_launch(void* const* d_in, const int* in_sizes, int n_in,
                              void* d_out, int out_size)
{
    const float* deltas = (const float*)d_in[0];
    const float* scores = (const float*)d_in[1];

    cudaMemsetAsync(d_out, 0, (size_t)out_size * sizeof(float), 0);
    void* p;
    cudaGetSymbolAddress(&p, g_hist);  cudaMemsetAsync(p, 0, sizeof(g_hist), 0);
    cudaGetSymbolAddress(&p, g_k64in); cudaMemsetAsync(p, 0, sizeof(g_k64in), 0);

    decode_kernel<<<NA / 256, 256>>>(deltas, scores);
    thresh_kernel<<<1, NBINS>>>();
    compact_kernel<<<NA / 256, 256>>>();

    void *d_temp = nullptr, *kin = nullptr, *kout = nullptr;
    cudaGetSymbolAddress(&d_temp, g_temp);
    cudaGetSymbolAddress(&kin,  g_k64in);
    cudaGetSymbolAddress(&kout, g_k64out);
    size_t tb = sizeof(g_temp);
    cub::DeviceRadixSort::SortKeysDescending(
        d_temp, tb, (const ull*)kin, (ull*)kout, NCAP, 0, 48, (cudaStream_t)0);

    gather_kernel<<<24, 256>>>();                       // 6144 threads

    mask_kernel<<<dim3(W1, (R1 + 255) / 256), 64>>>(0, R1, 0);
    compress_kernel<<<R1 * 32 / 256, 256>>>(0);
    scan1_kernel<<<1, 256>>>();

    mask_kernel<<<dim3(WORDS - W1, (TOPK + 255) / 256), 64>>>(W1, TOPK, 1);
    compress_kernel<<<(TOPK * 32 + 255) / 256, 256>>>(1);
    scan2_kernel<<<1, 256>>>((float*)d_out);
}

// round 5
// speedup vs baseline: 3.9406x; 1.1266x over previous
#include <cuda_runtime.h>
#include <cub/cub.cuh>
#include <math_constants.h>
#include <cstdint>

#define NA    36864      // 64*64*9 proposals
#define TOPK  6000
#define POST  2000
#define WORDS 94         // ceil(6000/64)
#define NCAP  8192       // compacted sort capacity
#define NBINS 1024

typedef unsigned long long ull;

// ---------------- static device scratch (no allocations allowed) ----------------
__device__ float4   g_props[NA];
__device__ unsigned g_skey[NA];
__device__ unsigned g_hist[NBINS + 1];      // [NBINS] = compact counter
__device__ int      g_B;
__device__ ull      g_k64in[NCAP], g_k64out[NCAP];
__device__ __align__(256) unsigned char g_temp[4u << 20];
__device__ float4   g_box[TOPK];
__device__ float    g_bar[TOPK], g_bsc[TOPK];
__device__ ull      g_validm[96];
__device__ ull      g_mask[(size_t)TOPK * WORDS];
__device__ ulonglong2 g_re[(size_t)TOPK * WORDS];   // sparse row entries {bits, word}
__device__ int      g_rcnt[TOPK];

// anchor widths/heights: ratio {0.5:(23,12), 1:(16,16), 2:(11,22)} x scales {8,16,32}
__constant__ float c_aw[9] = {184.f,368.f,736.f,128.f,256.f,512.f, 88.f,176.f,352.f};
__constant__ float c_ah[9] = { 96.f,192.f,384.f,128.f,256.f,512.f,176.f,352.f,704.f};

// ---------------- 1) decode + filter + key pack + score histogram ----------------
__global__ void decode_kernel(const float* __restrict__ dl, const float* __restrict__ sc)
{
    int i = blockIdx.x * blockDim.x + threadIdx.x;
    if (i >= NA) return;
    int pix = i / 9;              // h*64 + w
    int a   = i - pix * 9;
    int w   = pix & 63;
    int h   = pix >> 6;

    float s  = sc[(9 + a) * 4096 + pix];
    float d0 = dl[(a * 4 + 0) * 4096 + pix];
    float d1 = dl[(a * 4 + 1) * 4096 + pix];
    float d2 = dl[(a * 4 + 2) * 4096 + pix];
    float d3 = dl[(a * 4 + 3) * 4096 + pix];

    float aw = c_aw[a], ah = c_ah[a];
    float acx = (float)(16 * w + 8);
    float acy = (float)(16 * h + 8);

    // replicate reference fp32 op order exactly (no FMA contraction)
    float pcx = __fadd_rn(__fmul_rn(d0, aw), acx);
    float pcy = __fadd_rn(__fmul_rn(d1, ah), acy);
    float pw  = __fmul_rn(expf(d2), aw);
    float ph  = __fmul_rn(expf(d3), ah);
    float hw  = __fmul_rn(0.5f, pw);
    float hh  = __fmul_rn(0.5f, ph);

    float x1 = fminf(fmaxf(__fsub_rn(pcx, hw), 0.0f), 1023.0f);
    float y1 = fminf(fmaxf(__fsub_rn(pcy, hh), 0.0f), 1023.0f);
    float x2 = fminf(fmaxf(__fadd_rn(pcx, hw), 0.0f), 1023.0f);
    float y2 = fminf(fmaxf(__fadd_rn(pcy, hh), 0.0f), 1023.0f);

    g_props[i] = make_float4(x1, y1, x2, y2);

    bool keep = (__fadd_rn(__fsub_rn(x2, x1), 1.0f) >= 16.0f) &&
                (__fadd_rn(__fsub_rn(y2, y1), 1.0f) >= 16.0f);
    float sm = keep ? s : -CUDART_INF_F;

    unsigned b   = __float_as_uint(sm);
    unsigned ord = (b & 0x80000000u) ? ~b : (b | 0x80000000u);
    g_skey[i] = ord;
    if (keep) {
        int bin = min(NBINS - 1, (int)(s * (float)NBINS));   // s in [0,1)
        atomicAdd(&g_hist[bin], 1u);
    }
}

// ---------------- 1b) threshold bin: largest B with suffix-count >= TOPK ----------------
__global__ void thresh_kernel()
{
    __shared__ unsigned sh[NBINS];
    __shared__ int sB;
    int t = threadIdx.x;
    sh[t] = g_hist[t];
    if (t == 0) sB = 0;
    __syncthreads();
    for (int off = 1; off < NBINS; off <<= 1) {
        unsigned v = sh[t] + ((t + off < NBINS) ? sh[t + off] : 0u);
        __syncthreads();
        sh[t] = v;
        __syncthreads();
    }
    if (sh[t] >= TOPK) atomicMax(&sB, t);
    __syncthreads();
    if (t == 0) g_B = sB;
}

// ---------------- 1c) compact candidates above threshold bin ----------------
__global__ void compact_kernel()
{
    int i = blockIdx.x * blockDim.x + threadIdx.x;
    if (i >= NA) return;
    unsigned ord = g_skey[i];
    if (!(ord & 0x80000000u)) return;             // filtered (-inf)
    float s = __uint_as_float(ord & 0x7FFFFFFFu);
    int bin = min(NBINS - 1, (int)(s * (float)NBINS));
    if (bin < g_B) return;
    unsigned pos = atomicAdd(&g_hist[NBINS], 1u);
    if (pos < NCAP)
        g_k64in[pos] = ((ull)ord << 16) | (unsigned)((~i) & 0xFFFF);  // NA < 65536
}

// ---------------- 2) gather top-6000 into SoA + valid bitmask ----------------
__global__ void gather_kernel()
{
    int t = blockIdx.x * blockDim.x + threadIdx.x;   // 6144 threads
    float s; float4 p = make_float4(0.f, 0.f, 0.f, 0.f);
    if (t < TOPK) {
        ull k = g_k64out[t];
        unsigned idx = (~(unsigned)k) & 0xFFFFu;
        unsigned ord = (unsigned)(k >> 16);
        unsigned b   = (ord & 0x80000000u) ? (ord & 0x7FFFFFFFu) : ~ord;
        s = __uint_as_float(b);
        if (idx < NA) p = g_props[idx];
        else s = CUDART_NAN_F;                       // padding slot
    } else s = CUDART_NAN_F;
    bool v = isfinite(s);
    unsigned bal = __ballot_sync(0xFFFFFFFFu, v);
    if ((t & 31) == 0) ((unsigned*)g_validm)[t >> 5] = bal;
    if (t < TOPK) {
        g_box[t] = p; g_bsc[t] = s;
        g_bar[t] = __fmul_rn(__fadd_rn(__fsub_rn(p.z, p.x), 1.0f),
                             __fadd_rn(__fsub_rn(p.w, p.y), 1.0f));
    }
}

// ---------------- 3) suppression bitmask tiles (4 rows/thread, guarded fast-div) ----------------
__global__ void mask_kernel()
{
    int wd = blockIdx.x;
    int rowBase = blockIdx.y * 256;
    if (rowBase >= (wd + 1) * 64) return;           // tile fully below diagonal
    int tid = threadIdx.x;

    __shared__ float4 sc4[64];
    __shared__ float  scar[64];
    int j = wd * 64 + tid;
    if (j < TOPK) { sc4[tid] = g_box[j]; scar[tid] = g_bar[j]; }
    else { sc4[tid] = make_float4(3e9f, 3e9f, -3e9f, -3e9f); scar[tid] = 1.0f; }
    __syncthreads();

    float4 rb[4]; float rar[4]; ull acc[4], allowed[4]; int irow[4]; bool valid[4];
    #pragma unroll
    for (int r = 0; r < 4; r++) {
        int i = rowBase + r * 64 + tid;
        irow[r] = i;
        bool v = (i < TOPK);
        valid[r] = v;
        rb[r]  = v ? g_box[i] : make_float4(3e9f, 3e9f, -3e9f, -3e9f);
        rar[r] = v ? g_bar[i] : 1.0f;
        int sh = i - wd * 64 + 1;                   // keep bits kk >= sh (j > i)
        allowed[r] = (sh <= 0) ? ~0ULL : (sh >= 64 ? 0ULL : (~0ULL << sh));
        acc[r] = 0ULL;
    }

    #pragma unroll 4
    for (int kk = 0; kk < 64; kk++) {
        float4 c = sc4[kk]; float car = scar[kk];
        #pragma unroll
        for (int r = 0; r < 4; r++) {
            float iw = fmaxf(__fadd_rn(__fsub_rn(fminf(rb[r].z, c.z), fmaxf(rb[r].x, c.x)), 1.0f), 0.0f);
            float ih = fmaxf(__fadd_rn(__fsub_rn(fminf(rb[r].w, c.w), fmaxf(rb[r].y, c.y)), 1.0f), 0.0f);
            float inter = __fmul_rn(iw, ih);
            float un = __fsub_rn(__fadd_rn(rar[r], car), inter);
            float t = 0.7f * un;
            bool sup;
            if (inter > t * 1.0001f)       sup = true;    // surely > 0.7
            else if (inter <= t * 0.9999f) sup = false;   // surely <= 0.7
            else sup = (__fdiv_rn(inter, un) > 0.7f);     // rare exact path
            if (sup) acc[r] |= (1ULL << kk);
        }
    }
    #pragma unroll
    for (int r = 0; r < 4; r++)
        if (valid[r]) g_mask[(size_t)irow[r] * WORDS + wd] = acc[r] & allowed[r];
}

// ---------------- 3b) compress rows to sparse (word,bits) entry lists ----------------
__global__ void compress_kernel()
{
    int gi = blockIdx.x * blockDim.x + threadIdx.x;
    int i = gi >> 5, lane = gi & 31;
    if (i >= TOPK) return;
    int wlo = (i >> 6) + 1;
    int cnt = 0;
    for (int base = wlo; base < WORDS; base += 32) {
        int wd = base + lane;
        ull m = (wd < WORDS) ? g_mask[(size_t)i * WORDS + wd] : 0ULL;
        unsigned bal = __ballot_sync(0xFFFFFFFFu, m != 0ULL);
        if (m) g_re[(size_t)i * WORDS + cnt + __popc(bal & ((1u << lane) - 1u))] =
                   make_ulonglong2(m, (ull)wd);
        cnt += __popc(bal);
    }
    if (!lane) g_rcnt[i] = cnt;
}

// ---------------- 4) blocked greedy scan: MLP-parallel sparse application ----------------
__global__ void __launch_bounds__(256) scan_kernel(float* __restrict__ out)
{
    __shared__ ull removed[WORDS];
    __shared__ ull sval[WORDS];
    __shared__ ull sdiag[2][64];
    __shared__ unsigned s_rownz[2][2];
    __shared__ int s_slist[POST];
    __shared__ unsigned char s_rcnt[TOPK];
    __shared__ int s_count, s_c0;
    int tid = threadIdx.x, wid = tid >> 5, lane = tid & 31;

    // prefetch per-row entry counts into shared (removes a 600-cyc chain link)
    for (int t = tid; t < TOPK; t += 256) s_rcnt[t] = (unsigned char)g_rcnt[t];
    if (tid < WORDS) { removed[tid] = 0ULL; sval[tid] = g_validm[tid]; }
    if (!tid) { s_count = 0; s_c0 = 0; }
    if (tid >= 192) {                                // warps 6,7: diag block 0
        int t = tid - 192;
        ull dm = g_mask[(size_t)t * WORDS + 0];
        sdiag[0][t] = dm;
        unsigned bal = __ballot_sync(0xFFFFFFFFu, dm != 0ULL);
        if (!lane) s_rownz[0][wid - 6] = bal;
    }
    __syncthreads();

    int count = 0;
    for (int w = 0; w < WORDS; w++) {
        // Phase B: thread 0 resolves within-word greedy chain
        if (!tid) {
            ull alive = sval[w] & ~removed[w];
            ull rn = ((ull)s_rownz[w & 1][1] << 32) | s_rownz[w & 1][0];
            const ull* diag = sdiag[w & 1];
            int c = s_count; s_c0 = c;
            while (alive && c < POST) {
                int b = __ffsll(alive) - 1;
                ull bit = 1ULL << b;
                s_slist[c++] = w * 64 + b;
                alive &= ~bit;
                if (rn & bit) alive &= ~diag[b];
            }
            s_count = c;
        }
        __syncthreads();
        count = s_count;
        int c0 = s_c0;
        if (count >= POST) break;

        // Phase C: warps 6,7 prefetch next diag; warps 0..5 apply sparse rows,
        // 24 kept boxes in flight concurrently (4 per warp, 8 lanes each)
        if (tid >= 192) {
            if (w + 1 < WORDS) {
                int t = tid - 192;
                ull dm = g_mask[(size_t)((w + 1) * 64 + t) * WORDS + (w + 1)];
                sdiag[(w + 1) & 1][t] = dm;
                unsigned bal = __ballot_sync(0xFFFFFFFFu, dm != 0ULL);
                if (!lane) s_rownz[(w + 1) & 1][wid - 6] = bal;
            }
        } else {
            int nk = count - c0;
            for (int base = 0; base < nk; base += 24) {
                int slot = base + wid * 4 + (lane >> 3);
                if (slot < nk) {
                    int idx = s_slist[c0 + slot];
                    int cnt = s_rcnt[idx];
                    for (int e = (lane & 7); e < cnt; e += 8) {
                        ulonglong2 ent = g_re[(size_t)idx * WORDS + e];
                        atomicOr(&removed[(int)ent.y], ent.x);
                    }
                }
            }
        }
        __syncthreads();
    }

    // output
    int total = min(count, POST);
    float* outs = out + POST * 5;
    for (int t = tid; t < total; t += 256) {
        int i = s_slist[t];
        float4 p = g_box[i];
        out[t * 5 + 1] = p.x; out[t * 5 + 2] = p.y;
        out[t * 5 + 3] = p.z; out[t * 5 + 4] = p.w;
        outs[t] = g_bsc[i];
    }
}

// ---------------- launch ----------------
extern "C" void kernel_launch(void* const* d_in, const int* in_sizes, int n_in,
                              void* d_out, int out_size)
{
    const float* deltas = (const float*)d_in[0];
    const float* scores = (const float*)d_in[1];

    cudaMemsetAsync(d_out, 0, (size_t)out_size * sizeof(float), 0);
    void* p;
    cudaGetSymbolAddress(&p, g_hist);  cudaMemsetAsync(p, 0, sizeof(g_hist), 0);
    cudaGetSymbolAddress(&p, g_k64in); cudaMemsetAsync(p, 0, sizeof(g_k64in), 0);

    decode_kernel<<<NA / 256, 256>>>(deltas, scores);
    thresh_kernel<<<1, NBINS>>>();
    compact_kernel<<<NA / 256, 256>>>();

    void *d_temp = nullptr, *kin = nullptr, *kout = nullptr;
    cudaGetSymbolAddress(&d_temp, g_temp);
    cudaGetSymbolAddress(&kin,  g_k64in);
    cudaGetSymbolAddress(&kout, g_k64out);
    size_t tb = sizeof(g_temp);
    cub::DeviceRadixSort::SortKeysDescending(
        d_temp, tb, (const ull*)kin, (ull*)kout, NCAP, 0, 48, (cudaStream_t)0);

    gather_kernel<<<24, 256>>>();                       // 6144 threads

    mask_kernel<<<dim3(WORDS, (TOPK + 255) / 256), 64>>>();
    compress_kernel<<<TOPK * 32 / 256, 256>>>();
    scan_kernel<<<1, 256>>>((float*)d_out);
}

// round 6
// speedup vs baseline: 4.2345x; 1.0746x over previous
#include <cuda_runtime.h>
#include <math_constants.h>
#include <cstdint>

#define NA    36864      // 64*64*9 proposals
#define TOPK  6000
#define POST  2000
#define WORDS 94         // ceil(6000/64)
#define NCAP  8192       // compacted capacity (power of two)
#define NBINS 1024

typedef unsigned long long ull;

// ---------------- static device scratch (no allocations allowed) ----------------
__device__ float4   g_props[NA];
__device__ unsigned g_skey[NA];
__device__ unsigned g_hist[NBINS + 1];      // [NBINS] = compact counter
__device__ int      g_B;
__device__ ull      g_k64in[NCAP], g_k64out[NCAP];
__device__ float4   g_box[TOPK];
__device__ float    g_bar[TOPK], g_bsc[TOPK];
__device__ ull      g_validm[96];
__device__ ull      g_mask[(size_t)TOPK * WORDS];
__device__ ulonglong2 g_re[(size_t)TOPK * WORDS];   // sparse row entries {bits, word}
__device__ int      g_rcnt[TOPK];

// anchor widths/heights: ratio {0.5:(23,12), 1:(16,16), 2:(11,22)} x scales {8,16,32}
__constant__ float c_aw[9] = {184.f,368.f,736.f,128.f,256.f,512.f, 88.f,176.f,352.f};
__constant__ float c_ah[9] = { 96.f,192.f,384.f,128.f,256.f,512.f,176.f,352.f,704.f};

// ---------------- 1) decode + filter + key pack + score histogram ----------------
__global__ void decode_kernel(const float* __restrict__ dl, const float* __restrict__ sc)
{
    int i = blockIdx.x * blockDim.x + threadIdx.x;
    if (i >= NA) return;
    int pix = i / 9;              // h*64 + w
    int a   = i - pix * 9;
    int w   = pix & 63;
    int h   = pix >> 6;

    float s  = sc[(9 + a) * 4096 + pix];
    float d0 = dl[(a * 4 + 0) * 4096 + pix];
    float d1 = dl[(a * 4 + 1) * 4096 + pix];
    float d2 = dl[(a * 4 + 2) * 4096 + pix];
    float d3 = dl[(a * 4 + 3) * 4096 + pix];

    float aw = c_aw[a], ah = c_ah[a];
    float acx = (float)(16 * w + 8);
    float acy = (float)(16 * h + 8);

    // replicate reference fp32 op order exactly (no FMA contraction)
    float pcx = __fadd_rn(__fmul_rn(d0, aw), acx);
    float pcy = __fadd_rn(__fmul_rn(d1, ah), acy);
    float pw  = __fmul_rn(expf(d2), aw);
    float ph  = __fmul_rn(expf(d3), ah);
    float hw  = __fmul_rn(0.5f, pw);
    float hh  = __fmul_rn(0.5f, ph);

    float x1 = fminf(fmaxf(__fsub_rn(pcx, hw), 0.0f), 1023.0f);
    float y1 = fminf(fmaxf(__fsub_rn(pcy, hh), 0.0f), 1023.0f);
    float x2 = fminf(fmaxf(__fadd_rn(pcx, hw), 0.0f), 1023.0f);
    float y2 = fminf(fmaxf(__fadd_rn(pcy, hh), 0.0f), 1023.0f);

    g_props[i] = make_float4(x1, y1, x2, y2);

    bool keep = (__fadd_rn(__fsub_rn(x2, x1), 1.0f) >= 16.0f) &&
                (__fadd_rn(__fsub_rn(y2, y1), 1.0f) >= 16.0f);
    float sm = keep ? s : -CUDART_INF_F;

    unsigned b   = __float_as_uint(sm);
    unsigned ord = (b & 0x80000000u) ? ~b : (b | 0x80000000u);
    g_skey[i] = ord;
    if (keep) {
        int bin = min(NBINS - 1, (int)(s * (float)NBINS));   // s in [0,1)
        atomicAdd(&g_hist[bin], 1u);
    }
}

// ---------------- 1b) threshold bin: largest B with suffix-count >= TOPK ----------------
__global__ void thresh_kernel()
{
    __shared__ unsigned sh[NBINS];
    __shared__ int sB;
    int t = threadIdx.x;
    sh[t] = g_hist[t];
    if (t == 0) sB = 0;
    __syncthreads();
    for (int off = 1; off < NBINS; off <<= 1) {
        unsigned v = sh[t] + ((t + off < NBINS) ? sh[t + off] : 0u);
        __syncthreads();
        sh[t] = v;
        __syncthreads();
    }
    if (sh[t] >= TOPK) atomicMax(&sB, t);
    __syncthreads();
    if (t == 0) g_B = sB;
}

// ---------------- 1c) compact candidates above threshold bin ----------------
__global__ void compact_kernel()
{
    int i = blockIdx.x * blockDim.x + threadIdx.x;
    if (i >= NA) return;
    unsigned ord = g_skey[i];
    if (!(ord & 0x80000000u)) return;             // filtered (-inf)
    float s = __uint_as_float(ord & 0x7FFFFFFFu);
    int bin = min(NBINS - 1, (int)(s * (float)NBINS));
    if (bin < g_B) return;
    unsigned pos = atomicAdd(&g_hist[NBINS], 1u);
    if (pos < NCAP)
        g_k64in[pos] = ((ull)ord << 16) | (unsigned)((~i) & 0xFFFF);  // NA < 65536
}

// ---------------- 1d) O(N^2) exact rank + scatter == stable descending sort ----------------
// rank[i] = #{j : key_j > key_i} + #{j < i : key_j == key_i}  (padding zeros tie-broken)
__global__ void __launch_bounds__(256) rank_kernel()
{
    __shared__ int s_rank[32];
    int tid  = threadIdx.x;
    int item = blockIdx.x * 32 + (tid & 31);       // 32 items per block
    int q    = tid >> 5;                           // 8 key segments of 1024
    if (tid < 32) s_rank[tid] = 0;
    __syncthreads();

    ull ki = g_k64in[item];
    int j0 = q * (NCAP / 8);
    int r = 0;
    #pragma unroll 8
    for (int jj = 0; jj < NCAP / 8; jj++) {
        int j = j0 + jj;
        ull kj = __ldg(&g_k64in[j]);               // uniform address -> broadcast
        r += (kj > ki) || ((kj == ki) && (j < item));
    }
    atomicAdd(&s_rank[tid & 31], r);
    __syncthreads();
    if (tid < 32) g_k64out[s_rank[tid]] = ki;      // ranks form a permutation
}

// ---------------- 2) gather top-6000 into SoA + valid bitmask ----------------
__global__ void gather_kernel()
{
    int t = blockIdx.x * blockDim.x + threadIdx.x;   // 6144 threads
    float s; float4 p = make_float4(0.f, 0.f, 0.f, 0.f);
    if (t < TOPK) {
        ull k = g_k64out[t];
        unsigned idx = (~(unsigned)k) & 0xFFFFu;
        unsigned ord = (unsigned)(k >> 16);
        unsigned b   = (ord & 0x80000000u) ? (ord & 0x7FFFFFFFu) : ~ord;
        s = __uint_as_float(b);
        if (idx < NA) p = g_props[idx];
        else s = CUDART_NAN_F;                       // padding slot
    } else s = CUDART_NAN_F;
    bool v = isfinite(s);
    unsigned bal = __ballot_sync(0xFFFFFFFFu, v);
    if ((t & 31) == 0) ((unsigned*)g_validm)[t >> 5] = bal;
    if (t < TOPK) {
        g_box[t] = p; g_bsc[t] = s;
        g_bar[t] = __fmul_rn(__fadd_rn(__fsub_rn(p.z, p.x), 1.0f),
                             __fadd_rn(__fsub_rn(p.w, p.y), 1.0f));
    }
}

// ---------------- 3) suppression bitmask tiles (4 rows/thread, guarded fast-div) ----------------
__global__ void mask_kernel()
{
    int wd = blockIdx.x;
    int rowBase = blockIdx.y * 256;
    if (rowBase >= (wd + 1) * 64) return;           // tile fully below diagonal
    int tid = threadIdx.x;

    __shared__ float4 sc4[64];
    __shared__ float  scar[64];
    int j = wd * 64 + tid;
    if (j < TOPK) { sc4[tid] = g_box[j]; scar[tid] = g_bar[j]; }
    else { sc4[tid] = make_float4(3e9f, 3e9f, -3e9f, -3e9f); scar[tid] = 1.0f; }
    __syncthreads();

    float4 rb[4]; float rar[4]; ull acc[4], allowed[4]; int irow[4]; bool valid[4];
    #pragma unroll
    for (int r = 0; r < 4; r++) {
        int i = rowBase + r * 64 + tid;
        irow[r] = i;
        bool v = (i < TOPK);
        valid[r] = v;
        rb[r]  = v ? g_box[i] : make_float4(3e9f, 3e9f, -3e9f, -3e9f);
        rar[r] = v ? g_bar[i] : 1.0f;
        int sh = i - wd * 64 + 1;                   // keep bits kk >= sh (j > i)
        allowed[r] = (sh <= 0) ? ~0ULL : (sh >= 64 ? 0ULL : (~0ULL << sh));
        acc[r] = 0ULL;
    }

    #pragma unroll 4
    for (int kk = 0; kk < 64; kk++) {
        float4 c = sc4[kk]; float car = scar[kk];
        #pragma unroll
        for (int r = 0; r < 4; r++) {
            float iw = fmaxf(__fadd_rn(__fsub_rn(fminf(rb[r].z, c.z), fmaxf(rb[r].x, c.x)), 1.0f), 0.0f);
            float ih = fmaxf(__fadd_rn(__fsub_rn(fminf(rb[r].w, c.w), fmaxf(rb[r].y, c.y)), 1.0f), 0.0f);
            float inter = __fmul_rn(iw, ih);
            float un = __fsub_rn(__fadd_rn(rar[r], car), inter);
            float t = 0.7f * un;
            bool sup;
            if (inter > t * 1.0001f)       sup = true;    // surely > 0.7
            else if (inter <= t * 0.9999f) sup = false;   // surely <= 0.7
            else sup = (__fdiv_rn(inter, un) > 0.7f);     // rare exact path
            if (sup) acc[r] |= (1ULL << kk);
        }
    }
    #pragma unroll
    for (int r = 0; r < 4; r++)
        if (valid[r]) g_mask[(size_t)irow[r] * WORDS + wd] = acc[r] & allowed[r];
}

// ---------------- 3b) compress rows to sparse (word,bits) entry lists ----------------
__global__ void compress_kernel()
{
    int gi = blockIdx.x * blockDim.x + threadIdx.x;
    int i = gi >> 5, lane = gi & 31;
    if (i >= TOPK) return;
    int wlo = (i >> 6) + 1;
    int cnt = 0;
    for (int base = wlo; base < WORDS; base += 32) {
        int wd = base + lane;
        ull m = (wd < WORDS) ? g_mask[(size_t)i * WORDS + wd] : 0ULL;
        unsigned bal = __ballot_sync(0xFFFFFFFFu, m != 0ULL);
        if (m) g_re[(size_t)i * WORDS + cnt + __popc(bal & ((1u << lane) - 1u))] =
                   make_ulonglong2(m, (ull)wd);
        cnt += __popc(bal);
    }
    if (!lane) g_rcnt[i] = cnt;
}

// ---------------- 4) blocked greedy scan: MLP-parallel sparse application ----------------
__global__ void __launch_bounds__(256) scan_kernel(float* __restrict__ out)
{
    __shared__ ull removed[WORDS];
    __shared__ ull sval[WORDS];
    __shared__ ull sdiag[2][64];
    __shared__ unsigned s_rownz[2][2];
    __shared__ int s_slist[POST];
    __shared__ unsigned char s_rcnt[TOPK];
    __shared__ int s_count, s_c0;
    int tid = threadIdx.x, wid = tid >> 5, lane = tid & 31;

    // prefetch per-row entry counts into shared (removes a 600-cyc chain link)
    for (int t = tid; t < TOPK; t += 256) s_rcnt[t] = (unsigned char)g_rcnt[t];
    if (tid < WORDS) { removed[tid] = 0ULL; sval[tid] = g_validm[tid]; }
    if (!tid) { s_count = 0; s_c0 = 0; }
    if (tid >= 192) {                                // warps 6,7: diag block 0
        int t = tid - 192;
        ull dm = g_mask[(size_t)t * WORDS + 0];
        sdiag[0][t] = dm;
        unsigned bal = __ballot_sync(0xFFFFFFFFu, dm != 0ULL);
        if (!lane) s_rownz[0][wid - 6] = bal;
    }
    __syncthreads();

    int count = 0;
    for (int w = 0; w < WORDS; w++) {
        // Phase B: thread 0 resolves within-word greedy chain
        if (!tid) {
            ull alive = sval[w] & ~removed[w];
            ull rn = ((ull)s_rownz[w & 1][1] << 32) | s_rownz[w & 1][0];
            const ull* diag = sdiag[w & 1];
            int c = s_count; s_c0 = c;
            while (alive && c < POST) {
                int b = __ffsll(alive) - 1;
                ull bit = 1ULL << b;
                s_slist[c++] = w * 64 + b;
                alive &= ~bit;
                if (rn & bit) alive &= ~diag[b];
            }
            s_count = c;
        }
        __syncthreads();
        count = s_count;
        int c0 = s_c0;
        if (count >= POST) break;

        // Phase C: warps 6,7 prefetch next diag; warps 0..5 apply sparse rows,
        // 24 kept boxes in flight concurrently (4 per warp, 8 lanes each)
        if (tid >= 192) {
            if (w + 1 < WORDS) {
                int t = tid - 192;
                ull dm = g_mask[(size_t)((w + 1) * 64 + t) * WORDS + (w + 1)];
                sdiag[(w + 1) & 1][t] = dm;
                unsigned bal = __ballot_sync(0xFFFFFFFFu, dm != 0ULL);
                if (!lane) s_rownz[(w + 1) & 1][wid - 6] = bal;
            }
        } else {
            int nk = count - c0;
            for (int base = 0; base < nk; base += 24) {
                int slot = base + wid * 4 + (lane >> 3);
                if (slot < nk) {
                    int idx = s_slist[c0 + slot];
                    int cnt = s_rcnt[idx];
                    for (int e = (lane & 7); e < cnt; e += 8) {
                        ulonglong2 ent = g_re[(size_t)idx * WORDS + e];
                        atomicOr(&removed[(int)ent.y], ent.x);
                    }
                }
            }
        }
        __syncthreads();
    }

    // output
    int total = min(count, POST);
    float* outs = out + POST * 5;
    for (int t = tid; t < total; t += 256) {
        int i = s_slist[t];
        float4 p = g_box[i];
        out[t * 5 + 1] = p.x; out[t * 5 + 2] = p.y;
        out[t * 5 + 3] = p.z; out[t * 5 + 4] = p.w;
        outs[t] = g_bsc[i];
    }
}

// ---------------- launch ----------------
extern "C" void kernel_launch(void* const* d_in, const int* in_sizes, int n_in,
                              void* d_out, int out_size)
{
    const float* deltas = (const float*)d_in[0];
    const float* scores = (const float*)d_in[1];

    cudaMemsetAsync(d_out, 0, (size_t)out_size * sizeof(float), 0);
    void* p;
    cudaGetSymbolAddress(&p, g_hist);  cudaMemsetAsync(p, 0, sizeof(g_hist), 0);
    cudaGetSymbolAddress(&p, g_k64in); cudaMemsetAsync(p, 0, sizeof(g_k64in), 0);

    decode_kernel<<<NA / 256, 256>>>(deltas, scores);
    thresh_kernel<<<1, NBINS>>>();
    compact_kernel<<<NA / 256, 256>>>();
    rank_kernel<<<NCAP / 32, 256>>>();               // replaces CUB radix sort
    gather_kernel<<<24, 256>>>();                    // 6144 threads

    mask_kernel<<<dim3(WORDS, (TOPK + 255) / 256), 64>>>();
    compress_kernel<<<TOPK * 32 / 256, 256>>>();
    scan_kernel<<<1, 256>>>((float*)d_out);
}

// round 10
// speedup vs baseline: 4.4142x; 1.0424x over previous
#include <cuda_runtime.h>
#include <math_constants.h>
#include <cstdint>

#define NA    36864      // 64*64*9 proposals
#define TOPK  6000
#define POST  2000
#define WORDS 94         // ceil(6000/64)
#define NCAP  8192       // compacted capacity (power of two)
#define NBINS 1024

typedef unsigned long long ull;

// ---------------- static device scratch (no allocations allowed) ----------------
__device__ float4   g_props[NA];
__device__ unsigned g_skey[NA];
__device__ unsigned g_hist[NBINS + 1];      // [NBINS] = compact counter
__device__ int      g_B;
__device__ ull      g_k64in[NCAP], g_k64out[NCAP];
__device__ float4   g_box[TOPK];
__device__ float    g_bar[TOPK], g_bsc[TOPK];
__device__ ull      g_validm[96];
__device__ ull      g_mask[(size_t)TOPK * WORDS];
__device__ ulonglong2 g_re[(size_t)TOPK * WORDS];   // sparse row entries {bits, word}
__device__ int      g_rcnt[TOPK];

// anchor widths/heights: ratio {0.5:(23,12), 1:(16,16), 2:(11,22)} x scales {8,16,32}
__constant__ float c_aw[9] = {184.f,368.f,736.f,128.f,256.f,512.f, 88.f,176.f,352.f};
__constant__ float c_ah[9] = { 96.f,192.f,384.f,128.f,256.f,512.f,176.f,352.f,704.f};

// ---------------- 1) decode + filter + key pack + score histogram ----------------
__global__ void decode_kernel(const float* __restrict__ dl, const float* __restrict__ sc)
{
    int i = blockIdx.x * blockDim.x + threadIdx.x;
    if (i >= NA) return;
    int pix = i / 9;              // h*64 + w
    int a   = i - pix * 9;
    int w   = pix & 63;
    int h   = pix >> 6;

    float s  = sc[(9 + a) * 4096 + pix];
    float d0 = dl[(a * 4 + 0) * 4096 + pix];
    float d1 = dl[(a * 4 + 1) * 4096 + pix];
    float d2 = dl[(a * 4 + 2) * 4096 + pix];
    float d3 = dl[(a * 4 + 3) * 4096 + pix];

    float aw = c_aw[a], ah = c_ah[a];
    float acx = (float)(16 * w + 8);
    float acy = (float)(16 * h + 8);

    // replicate reference fp32 op order exactly (no FMA contraction)
    float pcx = __fadd_rn(__fmul_rn(d0, aw), acx);
    float pcy = __fadd_rn(__fmul_rn(d1, ah), acy);
    float pw  = __fmul_rn(expf(d2), aw);
    float ph  = __fmul_rn(expf(d3), ah);
    float hw  = __fmul_rn(0.5f, pw);
    float hh  = __fmul_rn(0.5f, ph);

    float x1 = fminf(fmaxf(__fsub_rn(pcx, hw), 0.0f), 1023.0f);
    float y1 = fminf(fmaxf(__fsub_rn(pcy, hh), 0.0f), 1023.0f);
    float x2 = fminf(fmaxf(__fadd_rn(pcx, hw), 0.0f), 1023.0f);
    float y2 = fminf(fmaxf(__fadd_rn(pcy, hh), 0.0f), 1023.0f);

    g_props[i] = make_float4(x1, y1, x2, y2);

    bool keep = (__fadd_rn(__fsub_rn(x2, x1), 1.0f) >= 16.0f) &&
                (__fadd_rn(__fsub_rn(y2, y1), 1.0f) >= 16.0f);
    float sm = keep ? s : -CUDART_INF_F;

    unsigned b   = __float_as_uint(sm);
    unsigned ord = (b & 0x80000000u) ? ~b : (b | 0x80000000u);
    g_skey[i] = ord;
    if (keep) {
        int bin = min(NBINS - 1, (int)(s * (float)NBINS));   // s in [0,1)
        atomicAdd(&g_hist[bin], 1u);
    }
}

// ---------------- 1b) threshold bin: largest B with suffix-count >= TOPK ----------------
__global__ void thresh_kernel()
{
    __shared__ unsigned sh[NBINS];
    __shared__ int sB;
    int t = threadIdx.x;
    sh[t] = g_hist[t];
    if (t == 0) sB = 0;
    __syncthreads();
    for (int off = 1; off < NBINS; off <<= 1) {
        unsigned v = sh[t] + ((t + off < NBINS) ? sh[t + off] : 0u);
        __syncthreads();
        sh[t] = v;
        __syncthreads();
    }
    if (sh[t] >= TOPK) atomicMax(&sB, t);
    __syncthreads();
    if (t == 0) g_B = sB;
}

// ---------------- 1c) compact candidates above threshold bin ----------------
__global__ void compact_kernel()
{
    int i = blockIdx.x * blockDim.x + threadIdx.x;
    if (i >= NA) return;
    unsigned ord = g_skey[i];
    if (!(ord & 0x80000000u)) return;             // filtered (-inf)
    float s = __uint_as_float(ord & 0x7FFFFFFFu);
    int bin = min(NBINS - 1, (int)(s * (float)NBINS));
    if (bin < g_B) return;
    unsigned pos = atomicAdd(&g_hist[NBINS], 1u);
    if (pos < NCAP)
        g_k64in[pos] = ((ull)ord << 16) | (unsigned)((~i) & 0xFFFF);  // NA < 65536
}

// ---------------- 1d) O(N^2) exact rank + scatter (R6 structure, 512 threads) ----------------
// rank[i] = #{j : key_j > key_i} + #{j < i : key_j == key_i}  (padding zeros tie-broken)
__global__ void __launch_bounds__(512) rank_kernel()
{
    __shared__ int s_rank[32];
    int tid  = threadIdx.x;
    int item = blockIdx.x * 32 + (tid & 31);       // 32 items per block
    int q    = tid >> 5;                           // 16 key segments of 512
    if (tid < 32) s_rank[tid] = 0;
    __syncthreads();

    ull ki = g_k64in[item];
    int j0 = q * (NCAP / 16);
    int r = 0;
    #pragma unroll 8
    for (int jj = 0; jj < NCAP / 16; jj++) {
        int j = j0 + jj;
        ull kj = __ldg(&g_k64in[j]);               // uniform address -> broadcast
        r += (kj > ki) || ((kj == ki) && (j < item));
    }
    atomicAdd(&s_rank[tid & 31], r);
    __syncthreads();
    if (tid < 32) g_k64out[s_rank[tid]] = ki;      // ranks form a permutation
}

// ---------------- 2) gather top-6000 into SoA + valid bitmask ----------------
__global__ void gather_kernel()
{
    int t = blockIdx.x * blockDim.x + threadIdx.x;   // 6144 threads
    float s; float4 p = make_float4(0.f, 0.f, 0.f, 0.f);
    if (t < TOPK) {
        ull k = g_k64out[t];
        unsigned idx = (~(unsigned)k) & 0xFFFFu;
        unsigned ord = (unsigned)(k >> 16);
        unsigned b   = (ord & 0x80000000u) ? (ord & 0x7FFFFFFFu) : ~ord;
        s = __uint_as_float(b);
        if (idx < NA) p = g_props[idx];
        else s = CUDART_NAN_F;                       // padding slot
    } else s = CUDART_NAN_F;
    bool v = isfinite(s);
    unsigned bal = __ballot_sync(0xFFFFFFFFu, v);
    if ((t & 31) == 0) ((unsigned*)g_validm)[t >> 5] = bal;
    if (t < TOPK) {
        g_box[t] = p; g_bsc[t] = s;
        g_bar[t] = __fmul_rn(__fadd_rn(__fsub_rn(p.z, p.x), 1.0f),
                             __fadd_rn(__fsub_rn(p.w, p.y), 1.0f));
    }
}

// ---------------- 3) suppression bitmask tiles (4 rows/thread, guarded fast-div) ----------------
__global__ void mask_kernel()
{
    int wd = blockIdx.x;
    int rowBase = blockIdx.y * 256;
    if (rowBase >= (wd + 1) * 64) return;           // tile fully below diagonal
    int tid = threadIdx.x;

    __shared__ float4 sc4[64];
    __shared__ float  scar[64];
    int j = wd * 64 + tid;
    if (j < TOPK) { sc4[tid] = g_box[j]; scar[tid] = g_bar[j]; }
    else { sc4[tid] = make_float4(3e9f, 3e9f, -3e9f, -3e9f); scar[tid] = 1.0f; }
    __syncthreads();

    float4 rb[4]; float rar[4]; ull acc[4], allowed[4]; int irow[4]; bool valid[4];
    #pragma unroll
    for (int r = 0; r < 4; r++) {
        int i = rowBase + r * 64 + tid;
        irow[r] = i;
        bool v = (i < TOPK);
        valid[r] = v;
        rb[r]  = v ? g_box[i] : make_float4(3e9f, 3e9f, -3e9f, -3e9f);
        rar[r] = v ? g_bar[i] : 1.0f;
        int sh = i - wd * 64 + 1;                   // keep bits kk >= sh (j > i)
        allowed[r] = (sh <= 0) ? ~0ULL : (sh >= 64 ? 0ULL : (~0ULL << sh));
        acc[r] = 0ULL;
    }

    #pragma unroll 4
    for (int kk = 0; kk < 64; kk++) {
        float4 c = sc4[kk]; float car = scar[kk];
        #pragma unroll
        for (int r = 0; r < 4; r++) {
            float iw = fmaxf(__fadd_rn(__fsub_rn(fminf(rb[r].z, c.z), fmaxf(rb[r].x, c.x)), 1.0f), 0.0f);
            float ih = fmaxf(__fadd_rn(__fsub_rn(fminf(rb[r].w, c.w), fmaxf(rb[r].y, c.y)), 1.0f), 0.0f);
            float inter = __fmul_rn(iw, ih);
            float un = __fsub_rn(__fadd_rn(rar[r], car), inter);
            float t = 0.7f * un;
            bool sup;
            if (inter > t * 1.0001f)       sup = true;    // surely > 0.7
            else if (inter <= t * 0.9999f) sup = false;   // surely <= 0.7
            else sup = (__fdiv_rn(inter, un) > 0.7f);     // rare exact path
            if (sup) acc[r] |= (1ULL << kk);
        }
    }
    #pragma unroll
    for (int r = 0; r < 4; r++)
        if (valid[r]) g_mask[(size_t)irow[r] * WORDS + wd] = acc[r] & allowed[r];
}

// ---------------- 3b) compress rows to sparse (word,bits) entry lists ----------------
__global__ void compress_kernel()
{
    int gi = blockIdx.x * blockDim.x + threadIdx.x;
    int i = gi >> 5, lane = gi & 31;
    if (i >= TOPK) return;
    int wlo = (i >> 6) + 1;
    int cnt = 0;
    for (int base = wlo; base < WORDS; base += 32) {
        int wd = base + lane;
        ull m = (wd < WORDS) ? g_mask[(size_t)i * WORDS + wd] : 0ULL;
        unsigned bal = __ballot_sync(0xFFFFFFFFu, m != 0ULL);
        if (m) g_re[(size_t)i * WORDS + cnt + __popc(bal & ((1u << lane) - 1u))] =
                   make_ulonglong2(m, (ull)wd);
        cnt += __popc(bal);
    }
    if (!lane) g_rcnt[i] = cnt;
}

// ---------------- 4) blocked greedy scan (R6 version; 48-slot Phase C) ----------------
__global__ void __launch_bounds__(256) scan_kernel(float* __restrict__ out)
{
    __shared__ ull removed[WORDS];
    __shared__ ull sval[WORDS];
    __shared__ ull sdiag[2][64];
    __shared__ unsigned s_rownz[2][2];
    __shared__ int s_slist[POST];
    __shared__ unsigned char s_rcnt[TOPK];
    __shared__ int s_count, s_c0;
    int tid = threadIdx.x, wid = tid >> 5, lane = tid & 31;

    for (int t = tid; t < TOPK; t += 256) s_rcnt[t] = (unsigned char)g_rcnt[t];
    if (tid < WORDS) { removed[tid] = 0ULL; sval[tid] = g_validm[tid]; }
    if (!tid) { s_count = 0; s_c0 = 0; }
    if (tid >= 192) {                                // warps 6,7: diag block 0
        int t = tid - 192;
        ull dm = g_mask[(size_t)t * WORDS + 0];
        sdiag[0][t] = dm;
        unsigned bal = __ballot_sync(0xFFFFFFFFu, dm != 0ULL);
        if (!lane) s_rownz[0][wid - 6] = bal;
    }
    __syncthreads();

    int count = 0;
    for (int w = 0; w < WORDS; w++) {
        // Phase B: thread 0 resolves within-word greedy chain
        if (!tid) {
            ull alive = sval[w] & ~removed[w];
            ull rn = ((ull)s_rownz[w & 1][1] << 32) | s_rownz[w & 1][0];
            const ull* diag = sdiag[w & 1];
            int c = s_count; s_c0 = c;
            while (alive && c < POST) {
                int b = __ffsll(alive) - 1;
                ull bit = 1ULL << b;
                s_slist[c++] = w * 64 + b;
                alive &= ~bit;
                if (rn & bit) alive &= ~diag[b];
            }
            s_count = c;
        }
        __syncthreads();
        count = s_count;
        int c0 = s_c0;
        if (count >= POST) break;

        // Phase C: warps 6,7 prefetch next diag; warps 0..5 apply sparse rows,
        // 48 kept-box slots concurrently (8 per warp, 4 lanes each)
        if (tid >= 192) {
            if (w + 1 < WORDS) {
                int t = tid - 192;
                int row = (w + 1) * 64 + t;
                ull dm = (row < TOPK) ? g_mask[(size_t)row * WORDS + (w + 1)] : 0ULL;
                sdiag[(w + 1) & 1][t] = dm;
                unsigned bal = __ballot_sync(0xFFFFFFFFu, dm != 0ULL);
                if (!lane) s_rownz[(w + 1) & 1][wid - 6] = bal;
            }
        } else {
            int nk = count - c0;
            for (int base = 0; base < nk; base += 48) {
                int slot = base + wid * 8 + (lane >> 2);
                if (slot < nk) {
                    int idx = s_slist[c0 + slot];
                    int cnt = s_rcnt[idx];
                    for (int e = (lane & 3); e < cnt; e += 4) {
                        ulonglong2 ent = g_re[(size_t)idx * WORDS + e];
                        atomicOr(&removed[(int)ent.y], ent.x);
                    }
                }
            }
        }
        __syncthreads();
    }

    // output
    int total = min(count, POST);
    float* outs = out + POST * 5;
    for (int t = tid; t < total; t += 256) {
        int i = s_slist[t];
        float4 p = g_box[i];
        out[t * 5 + 1] = p.x; out[t * 5 + 2] = p.y;
        out[t * 5 + 3] = p.z; out[t * 5 + 4] = p.w;
        outs[t] = g_bsc[i];
    }
}

// ---------------- launch ----------------
extern "C" void kernel_launch(void* const* d_in, const int* in_sizes, int n_in,
                              void* d_out, int out_size)
{
    const float* deltas = (const float*)d_in[0];
    const float* scores = (const float*)d_in[1];

    cudaMemsetAsync(d_out, 0, (size_t)out_size * sizeof(float), 0);
    void* p;
    cudaGetSymbolAddress(&p, g_hist);  cudaMemsetAsync(p, 0, sizeof(g_hist), 0);
    cudaGetSymbolAddress(&p, g_k64in); cudaMemsetAsync(p, 0, sizeof(g_k64in), 0);

    decode_kernel<<<NA / 256, 256>>>(deltas, scores);
    thresh_kernel<<<1, NBINS>>>();
    compact_kernel<<<NA / 256, 256>>>();
    rank_kernel<<<NCAP / 32, 512>>>();               // 256 blocks, 512 threads
    gather_kernel<<<24, 256>>>();                    // 6144 threads

    mask_kernel<<<dim3(WORDS, (TOPK + 255) / 256), 64>>>();
    compress_kernel<<<TOPK * 32 / 256, 256>>>();
    scan_kernel<<<1, 256>>>((float*)d_out);
}